// round 15
// baseline (speedup 1.0000x reference)
#include <cuda_runtime.h>
#include <cuda_fp16.h>
#include <math.h>
#include <stdint.h>

typedef uint32_t u32;

#define NH 3
#define NEMAX 200000
#define NCMAX 100000
#define BLKMAX 3125          // ceil(200000/64)

// ---------------- device scratch -----------------------------------------
__device__ float    g_gate[NH * NEMAX];
__device__ unsigned g_segmax[NH * NCMAX];
__device__ float    g_segsum[NH * NCMAX];

// frag-packed fp16 weights (single plane), per head 983040 bytes
#define HB 983040
__device__ __align__(16) uint2 g_w[3 * 122880];
// frag-packed layer0 fp16 activations (single plane): per 64-row block 49152 B
__device__ uint4 g_a0[(size_t)BLKMAX * 3072];

// matrix byte offsets within a head (fp16 single-plane, 8B frags)
#define B0 0
#define B1 196608
#define B2 393216
#define B5 786432
#define B6 851968
#define B7 917504
#define B8 950272
#define B9 966656

// ---------------- smem offsets (bytes) -------------------------------------
#define OFF_AH  0            // A plane, 64 rows x 256 cols fp16 = 32768
#define OFF_W   32768        // weight ping-pong, 2 x 16384
#define OFF_IDX 65536        // 64 ints
#define SMEMSZ  65792

#define NTH 256

// ---------------- helpers -------------------------------------------------
__device__ __forceinline__ u32 smem_u32(const void* p) {
    u32 a;
    asm("{ .reg .u64 t; cvta.to.shared.u64 t, %1; cvt.u32.u64 %0, t; }" : "=r"(a) : "l"(p));
    return a;
}
__device__ __forceinline__ u32 lds32(u32 a) {
    u32 v; asm volatile("ld.shared.b32 %0, [%1];" : "=r"(v) : "r"(a)); return v;
}
__device__ __forceinline__ uint2 lds64(u32 a) {
    uint2 v;
    asm volatile("ld.shared.v2.b32 {%0,%1}, [%2];" : "=r"(v.x), "=r"(v.y) : "r"(a));
    return v;
}
__device__ __forceinline__ uint4 lds128(u32 a) {
    uint4 v;
    asm volatile("ld.shared.v4.b32 {%0,%1,%2,%3}, [%4];"
                 : "=r"(v.x), "=r"(v.y), "=r"(v.z), "=r"(v.w) : "r"(a));
    return v;
}
__device__ __forceinline__ void sts32(u32 a, u32 v) {
    asm volatile("st.shared.b32 [%0], %1;" :: "r"(a), "r"(v) : "memory");
}
__device__ __forceinline__ void cp16(u32 dst, const void* src) {
    asm volatile("cp.async.cg.shared.global [%0], [%1], 16;" :: "r"(dst), "l"(src));
}
#define COMMIT()  asm volatile("cp.async.commit_group;" ::: "memory")
#define WAITG0()  asm volatile("cp.async.wait_group 0;" ::: "memory")

__device__ __forceinline__ void mma_f16(float c[4], const u32 a[4], u32 b0, u32 b1) {
    asm volatile(
        "mma.sync.aligned.m16n8k16.row.col.f32.f16.f16.f32 "
        "{%0,%1,%2,%3}, {%4,%5,%6,%7}, {%8,%9}, {%0,%1,%2,%3};"
        : "+f"(c[0]), "+f"(c[1]), "+f"(c[2]), "+f"(c[3])
        : "r"(a[0]), "r"(a[1]), "r"(a[2]), "r"(a[3]), "r"(b0), "r"(b1));
}

__device__ __forceinline__ float hflo(u32 v) {
    return __half2float(__ushort_as_half((unsigned short)(v & 0xFFFF)));
}
__device__ __forceinline__ float hfhi(u32 v) {
    return __half2float(__ushort_as_half((unsigned short)(v >> 16)));
}
__device__ __forceinline__ u32 h2pack(float a, float b) {
    __half2 h = __floats2half2_rn(a, b);
    return *(u32*)&h;
}
__device__ __forceinline__ unsigned fkey(float f) {
    unsigned u = __float_as_uint(f);
    return (u & 0x80000000u) ? ~u : (u | 0x80000000u);
}
__device__ __forceinline__ float funkey(unsigned u) {
    return (u & 0x80000000u) ? __uint_as_float(u & 0x7FFFFFFFu) : __uint_as_float(~u);
}

__device__ __forceinline__ void stage(u32 sdst, const void* src, int bytes, int tid) {
    const char* s = (const char*)src;
    for (int i = tid * 16; i < bytes; i += NTH * 16) cp16(sdst + i, s + i);
}

struct P {
    const float* elem; const int* ridx; const float* remb;
    const float *fcW0, *fcb0, *fcW1, *fcb1, *fcW2, *fcb2, *fcW3, *fcb3;
    const float *fcW4, *fcb4, *fcW5, *fcb5, *fcW6, *fcb6;
    const float *resW0, *resW4, *resW6, *outW, *outb;
    int n, c;
};

// ---------------- prep: weights -> frag-packed fp16 single plane -----------
__global__ void prep_w(P p)
{
    const int fid = blockIdx.x * 256 + threadIdx.x;
    const int h = blockIdx.y;
    if (fid >= 122880) return;
    const int fo[11] = {0,24576,49152,65536,81920,98304,106496,114688,118784,120832,122880};
    int m = 0;
    while (fid >= fo[m + 1]) m++;
    const int local = fid - fo[m];
    int K, N; const float* W;
    switch (m) {
        case 0: K=328; N=256; W=p.fcW0;  break;
        case 1: K=328; N=256; W=p.resW0; break;
        case 2: K=256; N=256; W=p.fcW1;  break;
        case 3: K=256; N=256; W=p.fcW2;  break;
        case 4: K=256; N=256; W=p.fcW3;  break;
        case 5: K=256; N=128; W=p.fcW4;  break;
        case 6: K=256; N=128; W=p.resW4; break;
        case 7: K=128; N=128; W=p.fcW5;  break;
        case 8: K=128; N=64;  W=p.fcW6;  break;
        default:K=128; N=64;  W=p.resW6; break;
    }
    int t, n, kt, kc;
    if (m < 2) {   // layer0: [kc][q][kt][64n][4t]
        t = local & 3;
        const int nl = (local >> 2) & 63;
        kt = (local >> 8) & 3;
        const int blkq = local >> 10;
        const int q = blkq & 3;
        kc = blkq >> 2;
        n = q * 64 + nl;
    } else {       // [kc][kt][N][4t]
        t = local & 3;
        int r = local >> 2;
        n = r % N; r /= N;
        kt = r & 3; kc = r >> 2;
    }
    const int k0 = kc * 64 + kt * 16 + 2 * t;
    const float* Wh = W + (size_t)h * K * N;
    const float v0 = (k0     < K) ? Wh[(size_t)k0 * N + n]       : 0.f;
    const float v1 = (k0 + 1 < K) ? Wh[(size_t)(k0 + 1) * N + n] : 0.f;
    const float v8 = (k0 + 8 < K) ? Wh[(size_t)(k0 + 8) * N + n] : 0.f;
    const float v9 = (k0 + 9 < K) ? Wh[(size_t)(k0 + 9) * N + n] : 0.f;
    uint2 o;
    o.x = h2pack(v0, v1);
    o.y = h2pack(v8, v9);
    *(uint2*)((char*)g_w + (size_t)h * HB + (size_t)fid * 8) = o;
}

// ---------------- prep: layer0 input -> frag-packed fp16 g_a0 --------------
// layout per block: [kc(6)][kt(4)][mt(4)][g(8)][t(4)] x 16B
__device__ __forceinline__ void ld2(const P& p, int e, int idx, int f, float& x, float& y)
{
    if (f < 200)      { x = p.elem[(size_t)e * 200 + f]; y = p.elem[(size_t)e * 200 + f + 1]; }
    else if (f < 328) { const float* r = p.remb + (size_t)idx * 128 + (f - 200); x = r[0]; y = r[1]; }
    else              { x = 0.f; y = 0.f; }
}

__global__ void prep_a0(P p)
{
    const int fi  = blockIdx.x * 256 + threadIdx.x;    // 0..3071
    const int blk = blockIdx.y;
    const int t  = fi & 3;
    const int g  = (fi >> 2) & 7;
    const int mt = (fi >> 5) & 3;
    const int kt = (fi >> 7) & 3;
    const int kc = fi >> 9;
    const int k0 = kc * 64 + kt * 16 + 2 * t;
    float v[2][4];
#pragma unroll
    for (int row = 0; row < 2; row++) {
        const int e = blk * 64 + mt * 16 + g + row * 8;
        if (e < p.n) {
            const int idx = p.ridx[e];
            ld2(p, e, idx, k0,     v[row][0], v[row][1]);
            ld2(p, e, idx, k0 + 8, v[row][2], v[row][3]);
        } else {
            v[row][0] = v[row][1] = v[row][2] = v[row][3] = 0.f;
        }
    }
    uint4 H;
    H.x = h2pack(v[0][0], v[0][1]);
    H.y = h2pack(v[1][0], v[1][1]);
    H.z = h2pack(v[0][2], v[0][3]);
    H.w = h2pack(v[1][2], v[1][3]);
    char* dst = (char*)g_a0 + (size_t)blk * 49152 + (size_t)fi * 16;
    *(uint4*)dst = H;
}

// ---------------- chunk MMA (A from smem plane, 2 m-tiles/warp) -------------
// A plane: per kt 2048B = [mt(4)][g(8)][t(4)] x 16B
template<int KT, int NT, bool DUAL>
__device__ __forceinline__ void mma_chunk_s(float accF[][4], float accR[][4],
                                            u32 abase, u32 wF, u32 wR,
                                            int N, int colOff, int mt0,
                                            int lane, int g, int t)
{
#pragma unroll
    for (int kt = 0; kt < KT; kt++) {
        const u32 aa = abase + kt * 2048 + (u32)(lane * 16) + (u32)(mt0 * 512);
        const uint4 ah0 = lds128(aa);
        const uint4 ah1 = lds128(aa + 512);
        const u32 aH0[4] = {ah0.x, ah0.y, ah0.z, ah0.w};
        const u32 aH1[4] = {ah1.x, ah1.y, ah1.z, ah1.w};
#pragma unroll
        for (int nt = 0; nt < NT; nt++) {
            const u32 off = (u32)(((kt * N + colOff + nt * 8 + g) * 4 + t) * 8);
            const uint2 wv = lds64(wF + off);
            mma_f16(accF[nt],      aH0, wv.x, wv.y);
            mma_f16(accF[NT + nt], aH1, wv.x, wv.y);
            if (DUAL) {
                const uint2 rv = lds64(wR + off);
                mma_f16(accR[nt],      aH0, rv.x, rv.y);
                mma_f16(accR[NT + nt], aH1, rv.x, rv.y);
            }
        }
    }
}

// ---------------- chunk MMA (A from gmem, layer 0, 2 m-tiles/warp) ----------
__device__ __forceinline__ void mma_chunk_r(float accF[][4], float accR[][4],
                                            const char* a0, int kc,
                                            u32 wF, u32 wR, int colOff, int mt0,
                                            int g, int t)
{
#pragma unroll
    for (int kt = 0; kt < 4; kt++) {
        const char* ap = a0 + (size_t)((((kc * 4 + kt) * 4 + mt0) * 8 + g) * 4 + t) * 16;
        const uint4 ah0 = *(const uint4*)ap;
        const uint4 ah1 = *(const uint4*)(ap + 512);
        const u32 aH0[4] = {ah0.x, ah0.y, ah0.z, ah0.w};
        const u32 aH1[4] = {ah1.x, ah1.y, ah1.z, ah1.w};
#pragma unroll
        for (int nt = 0; nt < 2; nt++) {
            const u32 off = (u32)(((kt * 64 + colOff + nt * 8 + g) * 4 + t) * 8);
            const uint2 wv = lds64(wF + off);
            mma_f16(accF[nt],     aH0, wv.x, wv.y);
            mma_f16(accF[2 + nt], aH1, wv.x, wv.y);
            const uint2 rv = lds64(wR + off);
            mma_f16(accR[nt],     aH0, rv.x, rv.y);
            mma_f16(accR[2 + nt], aH1, rv.x, rv.y);
        }
    }
}

// ---------------- epilogue: bias+relu+residual -> frag-packed A plane -------
template<int NT, bool DUAL>
__device__ __forceinline__ void epilogue(float accF[][4], float accR[][4],
                                         const float* bias, u32 sb, int colbase,
                                         int mt0, int g, int t)
{
#pragma unroll
    for (int mt = 0; mt < 2; mt++) {
#pragma unroll
        for (int nt = 0; nt < NT; nt++) {
            const int c0 = colbase + nt * 8 + t * 2;
            const float b0 = __ldg(bias + c0), b1 = __ldg(bias + c0 + 1);
            const int ai = mt * NT + nt;
            float v0 = fmaxf(accF[ai][0] + b0, 0.f);
            float v1 = fmaxf(accF[ai][1] + b1, 0.f);
            float v2 = fmaxf(accF[ai][2] + b0, 0.f);
            float v3 = fmaxf(accF[ai][3] + b1, 0.f);
            const u32 fb = sb + OFF_AH + (u32)((c0 >> 4) * 2048)
                         + (u32)(((mt0 + mt) * 32 + g * 4 + ((c0 & 7) >> 1)) * 16) + (u32)(c0 & 8);
            if (DUAL) {
                v0 += accR[ai][0]; v1 += accR[ai][1];
                v2 += accR[ai][2]; v3 += accR[ai][3];
            } else {
                const u32 ph0 = lds32(fb);
                const u32 ph1 = lds32(fb + 4);
                v0 += hflo(ph0); v1 += hfhi(ph0);
                v2 += hflo(ph1); v3 += hfhi(ph1);
            }
            sts32(fb,     h2pack(v0, v1));
            sts32(fb + 4, h2pack(v2, v3));
        }
    }
}

// ---------------- main fused MLP (M=64, 256 threads, 2 CTAs/SM) -------------
__global__ void __launch_bounds__(NTH, 2) mlp_tc(P p)
{
    extern __shared__ char sm[];
    const u32 sb  = smem_u32(sm);
    const int tid = threadIdx.x;
    const int lane = tid & 31, warp = tid >> 5;
    const int mt0 = (warp & 1) * 2;      // first 16-row m-tile of this warp
    const int cq  = warp >> 1;           // column quarter 0-3
    const int g = lane >> 2, t = lane & 3;
    const int h   = blockIdx.y;
    const int blk = blockIdx.x;
    const int n0  = blk * 64;

    int* idx_s = (int*)(sm + OFF_IDX);
    if (tid < 64) idx_s[tid] = (n0 + tid < p.n) ? p.ridx[n0 + tid] : 0;

    const char* gw = (const char*)g_w + (size_t)h * HB;
    const char* a0 = (const char*)g_a0 + (size_t)blk * 49152;

    int cc = 0;
#define WBUF(i)  (sb + OFF_W + (u32)(((i) & 1) * 16384))

    // prefetch L0 (q=0, kc=0): [fc][res]
    {
        u32 b = WBUF(0);
        stage(b,        gw + B0, 8192, tid);
        stage(b + 8192, gw + B1, 8192, tid);
        COMMIT();
    }

    // ===== layer 0: 384(pad) -> 256, fc + res, n-quarters, 24 phases =====
    for (int q = 0; q < 4; q++) {
        float accF[4][4], accR[4][4];
#pragma unroll
        for (int i = 0; i < 4; i++)
#pragma unroll
            for (int j = 0; j < 4; j++) { accF[i][j] = 0.f; accR[i][j] = 0.f; }
        for (int kc = 0; kc < 6; kc++) {
            WAITG0();
            __syncthreads();
            u32 nxt = WBUF(cc + 1);
            int nq = q, nkc = kc + 1;
            if (nkc == 6) { nq = q + 1; nkc = 0; }
            if (nq < 4) {
                stage(nxt,        gw + B0 + (nkc * 4 + nq) * 8192, 8192, tid);
                stage(nxt + 8192, gw + B1 + (nkc * 4 + nq) * 8192, 8192, tid);
            } else {
                stage(nxt, gw + B2, 16384, tid);
            }
            COMMIT();
            const u32 wB = WBUF(cc);
            mma_chunk_r(accF, accR, a0, kc, wB, wB + 8192, cq * 16, mt0, g, t);
            cc++;
        }
        __syncthreads();
        epilogue<2, true>(accF, accR, p.fcb0 + h * 256, sb, q * 64 + cq * 16, mt0, g, t);
        __syncthreads();
    }

    // ===== layers 1-3: 256 -> 256, identity residual, 8 phases each =====
    for (int l = 0; l < 3; l++) {
        const float* bias = (l == 0 ? p.fcb1 : l == 1 ? p.fcb2 : p.fcb3) + h * 256;
        const char* wl = gw + B2 + (size_t)l * 131072;
        float acc[16][4];
#pragma unroll
        for (int i = 0; i < 16; i++)
#pragma unroll
            for (int j = 0; j < 4; j++) acc[i][j] = 0.f;
        for (int c = 0; c < 8; c++) {
            WAITG0();
            __syncthreads();
            u32 nxt = WBUF(cc + 1);
            if (c < 7) {
                stage(nxt, wl + (c + 1) * 16384, 16384, tid);
            } else if (l < 2) {
                stage(nxt, wl + 131072, 16384, tid);
            } else {
                stage(nxt,        gw + B5, 8192, tid);
                stage(nxt + 8192, gw + B6, 8192, tid);
            }
            COMMIT();
            mma_chunk_s<2, 8, false>(acc, acc, sb + OFF_AH + c * 4096,
                                     WBUF(cc), 0, 256, cq * 64, mt0, lane, g, t);
            cc++;
        }
        __syncthreads();
        epilogue<8, false>(acc, acc, bias, sb, cq * 64, mt0, g, t);
        __syncthreads();
    }

    // ===== layer 4: 256 -> 128, fc + res, 8 phases =====
    {
        float accF[8][4], accR[8][4];
#pragma unroll
        for (int i = 0; i < 8; i++)
#pragma unroll
            for (int j = 0; j < 4; j++) { accF[i][j] = 0.f; accR[i][j] = 0.f; }
        for (int c = 0; c < 8; c++) {
            WAITG0();
            __syncthreads();
            u32 nxt = WBUF(cc + 1);
            if (c < 7) {
                stage(nxt,        gw + B5 + (c + 1) * 8192, 8192, tid);
                stage(nxt + 8192, gw + B6 + (c + 1) * 8192, 8192, tid);
            } else {
                stage(nxt, gw + B7, 16384, tid);
            }
            COMMIT();
            const u32 wB = WBUF(cc);
            mma_chunk_s<2, 4, true>(accF, accR, sb + OFF_AH + c * 4096,
                                    wB, wB + 8192, 128, cq * 32, mt0, lane, g, t);
            cc++;
        }
        __syncthreads();
        epilogue<4, true>(accF, accR, p.fcb4 + h * 128, sb, cq * 32, mt0, g, t);
        __syncthreads();
    }

    // ===== layer 5: 128 -> 128, identity, 2 phases =====
    {
        float acc[8][4];
#pragma unroll
        for (int i = 0; i < 8; i++)
#pragma unroll
            for (int j = 0; j < 4; j++) acc[i][j] = 0.f;
        for (int c = 0; c < 2; c++) {
            WAITG0();
            __syncthreads();
            u32 nxt = WBUF(cc + 1);
            if (c < 1) {
                stage(nxt, gw + B7 + 16384, 16384, tid);
            } else {
                stage(nxt,        gw + B8, 8192, tid);
                stage(nxt + 8192, gw + B9, 8192, tid);
            }
            COMMIT();
            mma_chunk_s<4, 4, false>(acc, acc, sb + OFF_AH + c * 8192,
                                     WBUF(cc), 0, 128, cq * 32, mt0, lane, g, t);
            cc++;
        }
        __syncthreads();
        epilogue<4, false>(acc, acc, p.fcb5 + h * 128, sb, cq * 32, mt0, g, t);
        __syncthreads();
    }

    // ===== layer 6: 128 -> 64, fc + res, 2 phases =====
    {
        float accF[4][4], accR[4][4];
#pragma unroll
        for (int i = 0; i < 4; i++)
#pragma unroll
            for (int j = 0; j < 4; j++) { accF[i][j] = 0.f; accR[i][j] = 0.f; }
        for (int c = 0; c < 2; c++) {
            WAITG0();
            __syncthreads();
            if (c < 1) {
                u32 nxt = WBUF(cc + 1);
                stage(nxt,        gw + B8 + 8192, 8192, tid);
                stage(nxt + 8192, gw + B9 + 8192, 8192, tid);
                COMMIT();
            }
            const u32 wB = WBUF(cc);
            mma_chunk_s<4, 2, true>(accF, accR, sb + OFF_AH + c * 8192,
                                    wB, wB + 8192, 64, cq * 16, mt0, lane, g, t);
            cc++;
        }
        __syncthreads();
        epilogue<2, true>(accF, accR, p.fcb6 + h * 64, sb, cq * 16, mt0, g, t);
        __syncthreads();
    }

    // ===== output head: gate = h . outW + outb =====
    if (tid < 64) {
        const int r = tid, e = n0 + r;
        if (e < p.n) {
            const int mt = r >> 4, g2 = r & 7, rh = (r & 15) >> 3;
            float acc = 0.f;
#pragma unroll
            for (int c = 0; c < 64; c += 2) {
                const u32 fb = sb + OFF_AH + (u32)((c >> 4) * 2048)
                             + (u32)((mt * 32 + g2 * 4 + ((c & 7) >> 1)) * 16)
                             + (u32)((c & 8) + rh * 4);
                const u32 ph = lds32(fb);
                acc = fmaf(hflo(ph), __ldg(p.outW + h * 64 + c), acc);
                acc = fmaf(hfhi(ph), __ldg(p.outW + h * 64 + c + 1), acc);
            }
            const float gate = acc + __ldg(p.outb + h);
            g_gate[h * p.n + e] = gate;
            atomicMax(&g_segmax[h * p.c + idx_s[r]], fkey(gate));
        }
    }
}

// ---------------- segment softmax epilogue ---------------------------------
__global__ void init_seg(int total)
{
    const int i = blockIdx.x * blockDim.x + threadIdx.x;
    if (i < total) { g_segmax[i] = 0u; g_segsum[i] = 0.f; }
}

__global__ void exp_kernel(const int* __restrict__ ridx, int n, int c)
{
    const int i = blockIdx.x * blockDim.x + threadIdx.x;
    if (i >= NH * n) return;
    const int hh = i / n;
    const int nn = i - hh * n;
    const int r  = ridx[nn];
    const float m = funkey(g_segmax[hh * c + r]);
    const float e = expf(g_gate[i] - m);
    g_gate[i] = e;
    atomicAdd(&g_segsum[hh * c + r], e);
}

__global__ void out_kernel(const int* __restrict__ ridx,
                           float* __restrict__ out, int n, int c)
{
    const int nn = blockIdx.x * blockDim.x + threadIdx.x;
    if (nn >= n) return;
    const int r = ridx[nn];
    float s = 0.f;
#pragma unroll
    for (int hh = 0; hh < NH; ++hh)
        s += g_gate[hh * n + nn] / (g_segsum[hh * c + r] + 1e-13f);
    out[nn] = s * (1.0f / 3.0f);
}

extern "C" void kernel_launch(void* const* d_in, const int* in_sizes, int n_in,
                              void* d_out, int out_size)
{
    P p;
    p.elem  = (const float*)d_in[0];
    p.ridx  = (const int*)  d_in[1];
    p.remb  = (const float*)d_in[2];
    p.fcW0  = (const float*)d_in[3];  p.fcb0 = (const float*)d_in[4];
    p.fcW1  = (const float*)d_in[5];  p.fcb1 = (const float*)d_in[6];
    p.fcW2  = (const float*)d_in[7];  p.fcb2 = (const float*)d_in[8];
    p.fcW3  = (const float*)d_in[9];  p.fcb3 = (const float*)d_in[10];
    p.fcW4  = (const float*)d_in[11]; p.fcb4 = (const float*)d_in[12];
    p.fcW5  = (const float*)d_in[13]; p.fcb5 = (const float*)d_in[14];
    p.fcW6  = (const float*)d_in[15]; p.fcb6 = (const float*)d_in[16];
    p.resW0 = (const float*)d_in[17];
    p.resW4 = (const float*)d_in[18];
    p.resW6 = (const float*)d_in[19];
    p.outW  = (const float*)d_in[20];
    p.outb  = (const float*)d_in[21];
    p.n = in_sizes[1];
    p.c = in_sizes[2] / 128;

    static bool init_done = false;
    if (!init_done) {
        cudaFuncSetAttribute(mlp_tc, cudaFuncAttributeMaxDynamicSharedMemorySize, SMEMSZ);
        init_done = true;
    }

    const int nblk = (p.n + 63) / 64;

    prep_w<<<dim3(480, NH), 256>>>(p);
    prep_a0<<<dim3(12, nblk), 256>>>(p);

    const int segs = NH * p.c;
    init_seg<<<(segs + 255) / 256, 256>>>(segs);

    mlp_tc<<<dim3(nblk, NH), NTH, SMEMSZ>>>(p);

    const int tot = NH * p.n;
    exp_kernel<<<(tot + 255) / 256, 256>>>(p.ridx, p.n, p.c);
    out_kernel<<<(p.n + 255) / 256, 256>>>(p.ridx, (float*)d_out, p.n, p.c);
}

// round 16
// speedup vs baseline: 1.5305x; 1.5305x over previous
#include <cuda_runtime.h>
#include <cuda_fp16.h>
#include <math.h>
#include <stdint.h>

typedef uint32_t u32;

#define NH 3
#define NEMAX 200000
#define NCMAX 100000
#define BLKMAX 3125          // ceil(200000/64)

// ---------------- device scratch -----------------------------------------
__device__ float    g_gate[NH * NEMAX];
__device__ unsigned g_segmax[NH * NCMAX];
__device__ float    g_segsum[NH * NCMAX];

// frag-packed fp16 weights (single plane), per head 983040 bytes
#define HB 983040
__device__ __align__(16) uint2 g_w[3 * 122880];
// frag-packed layer0 fp16 activations (single plane): per 64-row block 49152 B
__device__ uint4 g_a0[(size_t)BLKMAX * 3072];

// matrix byte offsets within a head (fp16 single-plane, 8B frags)
#define B0 0
#define B1 196608
#define B2 393216
#define B5 786432
#define B6 851968
#define B7 917504
#define B8 950272
#define B9 966656

// ---------------- smem offsets (bytes) -------------------------------------
#define OFF_AH  0            // A plane, 64 rows x 256 cols fp16 = 32768
#define OFF_W   32768        // weight ping-pong, 2 x 16384
#define OFF_IDX 65536        // 64 ints
#define SMEMSZ  65792

#define NTH 256

// ---------------- helpers -------------------------------------------------
__device__ __forceinline__ u32 smem_u32(const void* p) {
    u32 a;
    asm("{ .reg .u64 t; cvta.to.shared.u64 t, %1; cvt.u32.u64 %0, t; }" : "=r"(a) : "l"(p));
    return a;
}
__device__ __forceinline__ u32 lds32(u32 a) {
    u32 v; asm volatile("ld.shared.b32 %0, [%1];" : "=r"(v) : "r"(a)); return v;
}
__device__ __forceinline__ uint2 lds64(u32 a) {
    uint2 v;
    asm volatile("ld.shared.v2.b32 {%0,%1}, [%2];" : "=r"(v.x), "=r"(v.y) : "r"(a));
    return v;
}
__device__ __forceinline__ uint4 lds128(u32 a) {
    uint4 v;
    asm volatile("ld.shared.v4.b32 {%0,%1,%2,%3}, [%4];"
                 : "=r"(v.x), "=r"(v.y), "=r"(v.z), "=r"(v.w) : "r"(a));
    return v;
}
__device__ __forceinline__ void sts32(u32 a, u32 v) {
    asm volatile("st.shared.b32 [%0], %1;" :: "r"(a), "r"(v) : "memory");
}
__device__ __forceinline__ void cp16(u32 dst, const void* src) {
    asm volatile("cp.async.cg.shared.global [%0], [%1], 16;" :: "r"(dst), "l"(src));
}
#define COMMIT()  asm volatile("cp.async.commit_group;" ::: "memory")
#define WAITG0()  asm volatile("cp.async.wait_group 0;" ::: "memory")

__device__ __forceinline__ void mma_f16(float c[4], const u32 a[4], u32 b0, u32 b1) {
    asm volatile(
        "mma.sync.aligned.m16n8k16.row.col.f32.f16.f16.f32 "
        "{%0,%1,%2,%3}, {%4,%5,%6,%7}, {%8,%9}, {%0,%1,%2,%3};"
        : "+f"(c[0]), "+f"(c[1]), "+f"(c[2]), "+f"(c[3])
        : "r"(a[0]), "r"(a[1]), "r"(a[2]), "r"(a[3]), "r"(b0), "r"(b1));
}

__device__ __forceinline__ float hflo(u32 v) {
    return __half2float(__ushort_as_half((unsigned short)(v & 0xFFFF)));
}
__device__ __forceinline__ float hfhi(u32 v) {
    return __half2float(__ushort_as_half((unsigned short)(v >> 16)));
}
__device__ __forceinline__ u32 h2pack(float a, float b) {
    __half2 h = __floats2half2_rn(a, b);
    return *(u32*)&h;
}
__device__ __forceinline__ unsigned fkey(float f) {
    unsigned u = __float_as_uint(f);
    return (u & 0x80000000u) ? ~u : (u | 0x80000000u);
}
__device__ __forceinline__ float funkey(unsigned u) {
    return (u & 0x80000000u) ? __uint_as_float(u & 0x7FFFFFFFu) : __uint_as_float(~u);
}

__device__ __forceinline__ void stage(u32 sdst, const void* src, int bytes, int tid) {
    const char* s = (const char*)src;
    for (int i = tid * 16; i < bytes; i += NTH * 16) cp16(sdst + i, s + i);
}

struct P {
    const float* elem; const int* ridx; const float* remb;
    const float *fcW0, *fcb0, *fcW1, *fcb1, *fcW2, *fcb2, *fcW3, *fcb3;
    const float *fcW4, *fcb4, *fcW5, *fcb5, *fcW6, *fcb6;
    const float *resW0, *resW4, *resW6, *outW, *outb;
    int n, c;
};

// ---------------- prep: weights -> frag-packed fp16 single plane -----------
__global__ void prep_w(P p)
{
    const int fid = blockIdx.x * 256 + threadIdx.x;
    const int h = blockIdx.y;
    if (fid >= 122880) return;
    const int fo[11] = {0,24576,49152,65536,81920,98304,106496,114688,118784,120832,122880};
    int m = 0;
    while (fid >= fo[m + 1]) m++;
    const int local = fid - fo[m];
    int K, N; const float* W;
    switch (m) {
        case 0: K=328; N=256; W=p.fcW0;  break;
        case 1: K=328; N=256; W=p.resW0; break;
        case 2: K=256; N=256; W=p.fcW1;  break;
        case 3: K=256; N=256; W=p.fcW2;  break;
        case 4: K=256; N=256; W=p.fcW3;  break;
        case 5: K=256; N=128; W=p.fcW4;  break;
        case 6: K=256; N=128; W=p.resW4; break;
        case 7: K=128; N=128; W=p.fcW5;  break;
        case 8: K=128; N=64;  W=p.fcW6;  break;
        default:K=128; N=64;  W=p.resW6; break;
    }
    int t, n, kt, kc;
    if (m < 2) {   // layer0: [kc][q][kt][64n][4t]
        t = local & 3;
        const int nl = (local >> 2) & 63;
        kt = (local >> 8) & 3;
        const int blkq = local >> 10;
        const int q = blkq & 3;
        kc = blkq >> 2;
        n = q * 64 + nl;
    } else {       // [kc][kt][N][4t]
        t = local & 3;
        int r = local >> 2;
        n = r % N; r /= N;
        kt = r & 3; kc = r >> 2;
    }
    const int k0 = kc * 64 + kt * 16 + 2 * t;
    const float* Wh = W + (size_t)h * K * N;
    const float v0 = (k0     < K) ? Wh[(size_t)k0 * N + n]       : 0.f;
    const float v1 = (k0 + 1 < K) ? Wh[(size_t)(k0 + 1) * N + n] : 0.f;
    const float v8 = (k0 + 8 < K) ? Wh[(size_t)(k0 + 8) * N + n] : 0.f;
    const float v9 = (k0 + 9 < K) ? Wh[(size_t)(k0 + 9) * N + n] : 0.f;
    uint2 o;
    o.x = h2pack(v0, v1);
    o.y = h2pack(v8, v9);
    *(uint2*)((char*)g_w + (size_t)h * HB + (size_t)fid * 8) = o;
}

// ---------------- prep: layer0 input -> frag-packed fp16 g_a0 --------------
// layout per block: [kc(6)][kt(4)][mt(4)][g(8)][t(4)] x 16B
__device__ __forceinline__ void ld2(const P& p, int e, int idx, int f, float& x, float& y)
{
    if (f < 200)      { x = p.elem[(size_t)e * 200 + f]; y = p.elem[(size_t)e * 200 + f + 1]; }
    else if (f < 328) { const float* r = p.remb + (size_t)idx * 128 + (f - 200); x = r[0]; y = r[1]; }
    else              { x = 0.f; y = 0.f; }
}

__global__ void prep_a0(P p)
{
    const int fi  = blockIdx.x * 256 + threadIdx.x;    // 0..3071
    const int blk = blockIdx.y;
    const int t  = fi & 3;
    const int g  = (fi >> 2) & 7;
    const int mt = (fi >> 5) & 3;
    const int kt = (fi >> 7) & 3;
    const int kc = fi >> 9;
    const int k0 = kc * 64 + kt * 16 + 2 * t;
    float v[2][4];
#pragma unroll
    for (int row = 0; row < 2; row++) {
        const int e = blk * 64 + mt * 16 + g + row * 8;
        if (e < p.n) {
            const int idx = p.ridx[e];
            ld2(p, e, idx, k0,     v[row][0], v[row][1]);
            ld2(p, e, idx, k0 + 8, v[row][2], v[row][3]);
        } else {
            v[row][0] = v[row][1] = v[row][2] = v[row][3] = 0.f;
        }
    }
    uint4 H;
    H.x = h2pack(v[0][0], v[0][1]);
    H.y = h2pack(v[1][0], v[1][1]);
    H.z = h2pack(v[0][2], v[0][3]);
    H.w = h2pack(v[1][2], v[1][3]);
    char* dst = (char*)g_a0 + (size_t)blk * 49152 + (size_t)fi * 16;
    *(uint4*)dst = H;
}

// ---------------- chunk MMA (A from smem plane, 2 m-tiles/warp) -------------
// A plane: per kt 2048B = [mt(4)][g(8)][t(4)] x 16B
template<int KT, int NT, bool DUAL>
__device__ __forceinline__ void mma_chunk_s(float accF[][4], float accR[][4],
                                            u32 abase, u32 wF, u32 wR,
                                            int N, int colOff, int mt0,
                                            int lane, int g, int t)
{
#pragma unroll
    for (int kt = 0; kt < KT; kt++) {
        const u32 aa = abase + kt * 2048 + (u32)(lane * 16) + (u32)(mt0 * 512);
        const uint4 ah0 = lds128(aa);
        const uint4 ah1 = lds128(aa + 512);
        const u32 aH0[4] = {ah0.x, ah0.y, ah0.z, ah0.w};
        const u32 aH1[4] = {ah1.x, ah1.y, ah1.z, ah1.w};
#pragma unroll
        for (int nt = 0; nt < NT; nt++) {
            const u32 off = (u32)(((kt * N + colOff + nt * 8 + g) * 4 + t) * 8);
            const uint2 wv = lds64(wF + off);
            mma_f16(accF[nt],      aH0, wv.x, wv.y);
            mma_f16(accF[NT + nt], aH1, wv.x, wv.y);
            if (DUAL) {
                const uint2 rv = lds64(wR + off);
                mma_f16(accR[nt],      aH0, rv.x, rv.y);
                mma_f16(accR[NT + nt], aH1, rv.x, rv.y);
            }
        }
    }
}

// ---------------- chunk MMA (A from gmem, layer 0, 2 m-tiles/warp) ----------
__device__ __forceinline__ void mma_chunk_r(float accF[][4], float accR[][4],
                                            const char* a0, int kc,
                                            u32 wF, u32 wR, int colOff, int mt0,
                                            int g, int t)
{
#pragma unroll
    for (int kt = 0; kt < 4; kt++) {
        const char* ap = a0 + (size_t)((((kc * 4 + kt) * 4 + mt0) * 8 + g) * 4 + t) * 16;
        const uint4 ah0 = *(const uint4*)ap;
        const uint4 ah1 = *(const uint4*)(ap + 512);
        const u32 aH0[4] = {ah0.x, ah0.y, ah0.z, ah0.w};
        const u32 aH1[4] = {ah1.x, ah1.y, ah1.z, ah1.w};
#pragma unroll
        for (int nt = 0; nt < 2; nt++) {
            const u32 off = (u32)(((kt * 64 + colOff + nt * 8 + g) * 4 + t) * 8);
            const uint2 wv = lds64(wF + off);
            mma_f16(accF[nt],     aH0, wv.x, wv.y);
            mma_f16(accF[2 + nt], aH1, wv.x, wv.y);
            const uint2 rv = lds64(wR + off);
            mma_f16(accR[nt],     aH0, rv.x, rv.y);
            mma_f16(accR[2 + nt], aH1, rv.x, rv.y);
        }
    }
}

// ---------------- epilogue: bias+relu+residual -> frag-packed A plane -------
template<int NT, bool DUAL>
__device__ __forceinline__ void epilogue(float accF[][4], float accR[][4],
                                         const float* bias, u32 sb, int colbase,
                                         int mt0, int g, int t)
{
#pragma unroll
    for (int mt = 0; mt < 2; mt++) {
#pragma unroll
        for (int nt = 0; nt < NT; nt++) {
            const int c0 = colbase + nt * 8 + t * 2;
            const float b0 = __ldg(bias + c0), b1 = __ldg(bias + c0 + 1);
            const int ai = mt * NT + nt;
            float v0 = fmaxf(accF[ai][0] + b0, 0.f);
            float v1 = fmaxf(accF[ai][1] + b1, 0.f);
            float v2 = fmaxf(accF[ai][2] + b0, 0.f);
            float v3 = fmaxf(accF[ai][3] + b1, 0.f);
            const u32 fb = sb + OFF_AH + (u32)((c0 >> 4) * 2048)
                         + (u32)(((mt0 + mt) * 32 + g * 4 + ((c0 & 7) >> 1)) * 16) + (u32)(c0 & 8);
            if (DUAL) {
                v0 += accR[ai][0]; v1 += accR[ai][1];
                v2 += accR[ai][2]; v3 += accR[ai][3];
            } else {
                const u32 ph0 = lds32(fb);
                const u32 ph1 = lds32(fb + 4);
                v0 += hflo(ph0); v1 += hfhi(ph0);
                v2 += hflo(ph1); v3 += hfhi(ph1);
            }
            sts32(fb,     h2pack(v0, v1));
            sts32(fb + 4, h2pack(v2, v3));
        }
    }
}

// ---------------- main fused MLP (M=64, 256 threads, 2 CTAs/SM) -------------
__global__ void __launch_bounds__(NTH, 2) mlp_tc(P p)
{
    extern __shared__ char sm[];
    const u32 sb  = smem_u32(sm);
    const int tid = threadIdx.x;
    const int lane = tid & 31, warp = tid >> 5;
    const int mt0 = (warp & 1) * 2;      // first 16-row m-tile of this warp
    const int cq  = warp >> 1;           // column quarter 0-3
    const int g = lane >> 2, t = lane & 3;
    const int h   = blockIdx.y;
    const int blk = blockIdx.x;
    const int n0  = blk * 64;

    int* idx_s = (int*)(sm + OFF_IDX);
    if (tid < 64) idx_s[tid] = (n0 + tid < p.n) ? p.ridx[n0 + tid] : 0;

    const char* gw = (const char*)g_w + (size_t)h * HB;
    const char* a0 = (const char*)g_a0 + (size_t)blk * 49152;

    int cc = 0;
#define WBUF(i)  (sb + OFF_W + (u32)(((i) & 1) * 16384))

    // prefetch L0 (q=0, kc=0): [fc][res]
    {
        u32 b = WBUF(0);
        stage(b,        gw + B0, 8192, tid);
        stage(b + 8192, gw + B1, 8192, tid);
        COMMIT();
    }

    // ===== layer 0: 384(pad) -> 256, fc + res, n-quarters, 24 phases =====
    for (int q = 0; q < 4; q++) {
        float accF[4][4], accR[4][4];
#pragma unroll
        for (int i = 0; i < 4; i++)
#pragma unroll
            for (int j = 0; j < 4; j++) { accF[i][j] = 0.f; accR[i][j] = 0.f; }
        for (int kc = 0; kc < 6; kc++) {
            WAITG0();
            __syncthreads();
            u32 nxt = WBUF(cc + 1);
            int nq = q, nkc = kc + 1;
            if (nkc == 6) { nq = q + 1; nkc = 0; }
            if (nq < 4) {
                stage(nxt,        gw + B0 + (nkc * 4 + nq) * 8192, 8192, tid);
                stage(nxt + 8192, gw + B1 + (nkc * 4 + nq) * 8192, 8192, tid);
            } else {
                stage(nxt, gw + B2, 16384, tid);
            }
            COMMIT();
            const u32 wB = WBUF(cc);
            mma_chunk_r(accF, accR, a0, kc, wB, wB + 8192, cq * 16, mt0, g, t);
            cc++;
        }
        __syncthreads();
        epilogue<2, true>(accF, accR, p.fcb0 + h * 256, sb, q * 64 + cq * 16, mt0, g, t);
        __syncthreads();
    }

    // ===== layers 1-3: 256 -> 256, identity residual, 8 phases each =====
    for (int l = 0; l < 3; l++) {
        const float* bias = (l == 0 ? p.fcb1 : l == 1 ? p.fcb2 : p.fcb3) + h * 256;
        const char* wl = gw + B2 + (size_t)l * 131072;
        float acc[16][4];
#pragma unroll
        for (int i = 0; i < 16; i++)
#pragma unroll
            for (int j = 0; j < 4; j++) acc[i][j] = 0.f;
        for (int c = 0; c < 8; c++) {
            WAITG0();
            __syncthreads();
            u32 nxt = WBUF(cc + 1);
            if (c < 7) {
                stage(nxt, wl + (c + 1) * 16384, 16384, tid);
            } else if (l < 2) {
                stage(nxt, wl + 131072, 16384, tid);
            } else {
                stage(nxt,        gw + B5, 8192, tid);
                stage(nxt + 8192, gw + B6, 8192, tid);
            }
            COMMIT();
            mma_chunk_s<2, 8, false>(acc, acc, sb + OFF_AH + c * 4096,
                                     WBUF(cc), 0, 256, cq * 64, mt0, lane, g, t);
            cc++;
        }
        __syncthreads();
        epilogue<8, false>(acc, acc, bias, sb, cq * 64, mt0, g, t);
        __syncthreads();
    }

    // ===== layer 4: 256 -> 128, fc + res, 8 phases =====
    {
        float accF[8][4], accR[8][4];
#pragma unroll
        for (int i = 0; i < 8; i++)
#pragma unroll
            for (int j = 0; j < 4; j++) { accF[i][j] = 0.f; accR[i][j] = 0.f; }
        for (int c = 0; c < 8; c++) {
            WAITG0();
            __syncthreads();
            u32 nxt = WBUF(cc + 1);
            if (c < 7) {
                stage(nxt,        gw + B5 + (c + 1) * 8192, 8192, tid);
                stage(nxt + 8192, gw + B6 + (c + 1) * 8192, 8192, tid);
            } else {
                stage(nxt, gw + B7, 16384, tid);
            }
            COMMIT();
            const u32 wB = WBUF(cc);
            mma_chunk_s<2, 4, true>(accF, accR, sb + OFF_AH + c * 4096,
                                    wB, wB + 8192, 128, cq * 32, mt0, lane, g, t);
            cc++;
        }
        __syncthreads();
        epilogue<4, true>(accF, accR, p.fcb4 + h * 128, sb, cq * 32, mt0, g, t);
        __syncthreads();
    }

    // ===== layer 5: 128 -> 128, identity, 2 phases =====
    {
        float acc[8][4];
#pragma unroll
        for (int i = 0; i < 8; i++)
#pragma unroll
            for (int j = 0; j < 4; j++) acc[i][j] = 0.f;
        for (int c = 0; c < 2; c++) {
            WAITG0();
            __syncthreads();
            u32 nxt = WBUF(cc + 1);
            if (c < 1) {
                stage(nxt, gw + B7 + 16384, 16384, tid);
            } else {
                stage(nxt,        gw + B8, 8192, tid);
                stage(nxt + 8192, gw + B9, 8192, tid);
            }
            COMMIT();
            mma_chunk_s<4, 4, false>(acc, acc, sb + OFF_AH + c * 8192,
                                     WBUF(cc), 0, 128, cq * 32, mt0, lane, g, t);
            cc++;
        }
        __syncthreads();
        epilogue<4, false>(acc, acc, p.fcb5 + h * 128, sb, cq * 32, mt0, g, t);
        __syncthreads();
    }

    // ===== layer 6: 128 -> 64, fc + res, 2 phases =====
    {
        float accF[4][4], accR[4][4];
#pragma unroll
        for (int i = 0; i < 4; i++)
#pragma unroll
            for (int j = 0; j < 4; j++) { accF[i][j] = 0.f; accR[i][j] = 0.f; }
        for (int c = 0; c < 2; c++) {
            WAITG0();
            __syncthreads();
            if (c < 1) {
                u32 nxt = WBUF(cc + 1);
                stage(nxt,        gw + B8 + 8192, 8192, tid);
                stage(nxt + 8192, gw + B9 + 8192, 8192, tid);
                COMMIT();
            }
            const u32 wB = WBUF(cc);
            mma_chunk_s<4, 2, true>(accF, accR, sb + OFF_AH + c * 8192,
                                    wB, wB + 8192, 64, cq * 16, mt0, lane, g, t);
            cc++;
        }
        __syncthreads();
        epilogue<2, true>(accF, accR, p.fcb6 + h * 64, sb, cq * 16, mt0, g, t);
        __syncthreads();
    }

    // ===== output head: gate = h . outW + outb =====
    if (tid < 64) {
        const int r = tid, e = n0 + r;
        if (e < p.n) {
            const int mt = r >> 4, g2 = r & 7, rh = (r & 15) >> 3;
            float acc = 0.f;
#pragma unroll
            for (int c = 0; c < 64; c += 2) {
                const u32 fb = sb + OFF_AH + (u32)((c >> 4) * 2048)
                             + (u32)((mt * 32 + g2 * 4 + ((c & 7) >> 1)) * 16)
                             + (u32)((c & 8) + rh * 4);
                const u32 ph = lds32(fb);
                acc = fmaf(hflo(ph), __ldg(p.outW + h * 64 + c), acc);
                acc = fmaf(hfhi(ph), __ldg(p.outW + h * 64 + c + 1), acc);
            }
            const float gate = acc + __ldg(p.outb + h);
            g_gate[h * p.n + e] = gate;
            atomicMax(&g_segmax[h * p.c + idx_s[r]], fkey(gate));
        }
    }
}

// ---------------- segment softmax epilogue ---------------------------------
__global__ void init_seg(int total)
{
    const int i = blockIdx.x * blockDim.x + threadIdx.x;
    if (i < total) { g_segmax[i] = 0u; g_segsum[i] = 0.f; }
}

__global__ void exp_kernel(const int* __restrict__ ridx, int n, int c)
{
    const int i = blockIdx.x * blockDim.x + threadIdx.x;
    if (i >= NH * n) return;
    const int hh = i / n;
    const int nn = i - hh * n;
    const int r  = ridx[nn];
    const float m = funkey(g_segmax[hh * c + r]);
    const float e = expf(g_gate[i] - m);
    g_gate[i] = e;
    atomicAdd(&g_segsum[hh * c + r], e);
}

__global__ void out_kernel(const int* __restrict__ ridx,
                           float* __restrict__ out, int n, int c)
{
    const int nn = blockIdx.x * blockDim.x + threadIdx.x;
    if (nn >= n) return;
    const int r = ridx[nn];
    float s = 0.f;
#pragma unroll
    for (int hh = 0; hh < NH; ++hh)
        s += g_gate[hh * n + nn] / (g_segsum[hh * c + r] + 1e-13f);
    out[nn] = s * (1.0f / 3.0f);
}

extern "C" void kernel_launch(void* const* d_in, const int* in_sizes, int n_in,
                              void* d_out, int out_size)
{
    P p;
    p.elem  = (const float*)d_in[0];
    p.ridx  = (const int*)  d_in[1];
    p.remb  = (const float*)d_in[2];
    p.fcW0  = (const float*)d_in[3];  p.fcb0 = (const float*)d_in[4];
    p.fcW1  = (const float*)d_in[5];  p.fcb1 = (const float*)d_in[6];
    p.fcW2  = (const float*)d_in[7];  p.fcb2 = (const float*)d_in[8];
    p.fcW3  = (const float*)d_in[9];  p.fcb3 = (const float*)d_in[10];
    p.fcW4  = (const float*)d_in[11]; p.fcb4 = (const float*)d_in[12];
    p.fcW5  = (const float*)d_in[13]; p.fcb5 = (const float*)d_in[14];
    p.fcW6  = (const float*)d_in[15]; p.fcb6 = (const float*)d_in[16];
    p.resW0 = (const float*)d_in[17];
    p.resW4 = (const float*)d_in[18];
    p.resW6 = (const float*)d_in[19];
    p.outW  = (const float*)d_in[20];
    p.outb  = (const float*)d_in[21];
    p.n = in_sizes[1];
    p.c = in_sizes[2] / 128;

    static bool init_done = false;
    if (!init_done) {
        cudaFuncSetAttribute(mlp_tc, cudaFuncAttributeMaxDynamicSharedMemorySize, SMEMSZ);
        init_done = true;
    }

    const int nblk = (p.n + 63) / 64;

    prep_w<<<dim3(480, NH), 256>>>(p);
    prep_a0<<<dim3(12, nblk), 256>>>(p);

    const int segs = NH * p.c;
    init_seg<<<(segs + 255) / 256, 256>>>(segs);

    mlp_tc<<<dim3(nblk, NH), NTH, SMEMSZ>>>(p);

    const int tot = NH * p.n;
    exp_kernel<<<(tot + 255) / 256, 256>>>(p.ridx, p.n, p.c);
    out_kernel<<<(p.n + 255) / 256, 256>>>(p.ridx, (float*)d_out, p.n, p.c);
}

// round 17
// speedup vs baseline: 1.5335x; 1.0020x over previous
#include <cuda_runtime.h>
#include <cuda_fp16.h>
#include <math.h>
#include <stdint.h>

typedef uint32_t u32;

#define NH 3
#define NEMAX 200000
#define NCMAX 100000
#define BLKMAX 3125          // ceil(200000/64)

// ---------------- device scratch -----------------------------------------
__device__ float    g_gate[NH * NEMAX];
__device__ unsigned g_segmax[NH * NCMAX];
__device__ float    g_segsum[NH * NCMAX];

// frag-packed fp16 weights (single plane), per head 983040 bytes
#define HB 983040
__device__ __align__(16) uint2 g_w[3 * 122880];
// frag-packed layer0 fp16 activations (single plane): per 64-row block 49152 B
__device__ uint4 g_a0[(size_t)BLKMAX * 3072];

// matrix byte offsets within a head (fp16 single-plane, 8B frags)
#define B0 0
#define B1 196608
#define B2 393216
#define B5 786432
#define B6 851968
#define B7 917504
#define B8 950272
#define B9 966656

// ---------------- smem offsets (bytes) -------------------------------------
#define OFF_AH  0            // A plane, 64 rows x 256 cols fp16 = 32768
#define OFF_W   32768        // weight ping-pong, 2 x 16384
#define OFF_IDX 65536        // 64 ints
#define SMEMSZ  65792

#define NTH 256

// ---------------- helpers -------------------------------------------------
__device__ __forceinline__ u32 smem_u32(const void* p) {
    u32 a;
    asm("{ .reg .u64 t; cvta.to.shared.u64 t, %1; cvt.u32.u64 %0, t; }" : "=r"(a) : "l"(p));
    return a;
}
__device__ __forceinline__ u32 lds32(u32 a) {
    u32 v; asm volatile("ld.shared.b32 %0, [%1];" : "=r"(v) : "r"(a)); return v;
}
__device__ __forceinline__ uint2 lds64(u32 a) {
    uint2 v;
    asm volatile("ld.shared.v2.b32 {%0,%1}, [%2];" : "=r"(v.x), "=r"(v.y) : "r"(a));
    return v;
}
__device__ __forceinline__ uint4 lds128(u32 a) {
    uint4 v;
    asm volatile("ld.shared.v4.b32 {%0,%1,%2,%3}, [%4];"
                 : "=r"(v.x), "=r"(v.y), "=r"(v.z), "=r"(v.w) : "r"(a));
    return v;
}
__device__ __forceinline__ void sts32(u32 a, u32 v) {
    asm volatile("st.shared.b32 [%0], %1;" :: "r"(a), "r"(v) : "memory");
}
__device__ __forceinline__ void cp16(u32 dst, const void* src) {
    asm volatile("cp.async.cg.shared.global [%0], [%1], 16;" :: "r"(dst), "l"(src));
}
#define COMMIT()  asm volatile("cp.async.commit_group;" ::: "memory")
#define WAITG0()  asm volatile("cp.async.wait_group 0;" ::: "memory")

__device__ __forceinline__ void mma_f16(float c[4], const u32 a[4], u32 b0, u32 b1) {
    asm volatile(
        "mma.sync.aligned.m16n8k16.row.col.f32.f16.f16.f32 "
        "{%0,%1,%2,%3}, {%4,%5,%6,%7}, {%8,%9}, {%0,%1,%2,%3};"
        : "+f"(c[0]), "+f"(c[1]), "+f"(c[2]), "+f"(c[3])
        : "r"(a[0]), "r"(a[1]), "r"(a[2]), "r"(a[3]), "r"(b0), "r"(b1));
}

__device__ __forceinline__ float hflo(u32 v) {
    return __half2float(__ushort_as_half((unsigned short)(v & 0xFFFF)));
}
__device__ __forceinline__ float hfhi(u32 v) {
    return __half2float(__ushort_as_half((unsigned short)(v >> 16)));
}
__device__ __forceinline__ u32 h2pack(float a, float b) {
    __half2 h = __floats2half2_rn(a, b);
    return *(u32*)&h;
}
__device__ __forceinline__ unsigned fkey(float f) {
    unsigned u = __float_as_uint(f);
    return (u & 0x80000000u) ? ~u : (u | 0x80000000u);
}
__device__ __forceinline__ float funkey(unsigned u) {
    return (u & 0x80000000u) ? __uint_as_float(u & 0x7FFFFFFFu) : __uint_as_float(~u);
}

__device__ __forceinline__ void stage(u32 sdst, const void* src, int bytes, int tid) {
    const char* s = (const char*)src;
    for (int i = tid * 16; i < bytes; i += NTH * 16) cp16(sdst + i, s + i);
}

struct P {
    const float* elem; const int* ridx; const float* remb;
    const float *fcW0, *fcb0, *fcW1, *fcb1, *fcW2, *fcb2, *fcW3, *fcb3;
    const float *fcW4, *fcb4, *fcW5, *fcb5, *fcW6, *fcb6;
    const float *resW0, *resW4, *resW6, *outW, *outb;
    int n, c;
};

// ---------------- prep: weights -> frag-packed fp16 single plane -----------
__global__ void prep_w(P p)
{
    const int fid = blockIdx.x * 256 + threadIdx.x;
    const int h = blockIdx.y;
    if (fid >= 122880) return;
    const int fo[11] = {0,24576,49152,65536,81920,98304,106496,114688,118784,120832,122880};
    int m = 0;
    while (fid >= fo[m + 1]) m++;
    const int local = fid - fo[m];
    int K, N; const float* W;
    switch (m) {
        case 0: K=328; N=256; W=p.fcW0;  break;
        case 1: K=328; N=256; W=p.resW0; break;
        case 2: K=256; N=256; W=p.fcW1;  break;
        case 3: K=256; N=256; W=p.fcW2;  break;
        case 4: K=256; N=256; W=p.fcW3;  break;
        case 5: K=256; N=128; W=p.fcW4;  break;
        case 6: K=256; N=128; W=p.resW4; break;
        case 7: K=128; N=128; W=p.fcW5;  break;
        case 8: K=128; N=64;  W=p.fcW6;  break;
        default:K=128; N=64;  W=p.resW6; break;
    }
    int t, n, kt, kc;
    if (m < 2) {   // layer0: [kc][q][kt][64n][4t]
        t = local & 3;
        const int nl = (local >> 2) & 63;
        kt = (local >> 8) & 3;
        const int blkq = local >> 10;
        const int q = blkq & 3;
        kc = blkq >> 2;
        n = q * 64 + nl;
    } else {       // [kc][kt][N][4t]
        t = local & 3;
        int r = local >> 2;
        n = r % N; r /= N;
        kt = r & 3; kc = r >> 2;
    }
    const int k0 = kc * 64 + kt * 16 + 2 * t;
    const float* Wh = W + (size_t)h * K * N;
    const float v0 = (k0     < K) ? Wh[(size_t)k0 * N + n]       : 0.f;
    const float v1 = (k0 + 1 < K) ? Wh[(size_t)(k0 + 1) * N + n] : 0.f;
    const float v8 = (k0 + 8 < K) ? Wh[(size_t)(k0 + 8) * N + n] : 0.f;
    const float v9 = (k0 + 9 < K) ? Wh[(size_t)(k0 + 9) * N + n] : 0.f;
    uint2 o;
    o.x = h2pack(v0, v1);
    o.y = h2pack(v8, v9);
    *(uint2*)((char*)g_w + (size_t)h * HB + (size_t)fid * 8) = o;
}

// ---------------- prep: layer0 input -> frag-packed fp16 g_a0 --------------
// layout per block: [kc(6)][kt(4)][mt(4)][g(8)][t(4)] x 16B
__device__ __forceinline__ void ld2(const P& p, int e, int idx, int f, float& x, float& y)
{
    if (f < 200)      { x = p.elem[(size_t)e * 200 + f]; y = p.elem[(size_t)e * 200 + f + 1]; }
    else if (f < 328) { const float* r = p.remb + (size_t)idx * 128 + (f - 200); x = r[0]; y = r[1]; }
    else              { x = 0.f; y = 0.f; }
}

__global__ void prep_a0(P p)
{
    const int fi  = blockIdx.x * 256 + threadIdx.x;    // 0..3071
    const int blk = blockIdx.y;
    const int t  = fi & 3;
    const int g  = (fi >> 2) & 7;
    const int mt = (fi >> 5) & 3;
    const int kt = (fi >> 7) & 3;
    const int kc = fi >> 9;
    const int k0 = kc * 64 + kt * 16 + 2 * t;
    float v[2][4];
#pragma unroll
    for (int row = 0; row < 2; row++) {
        const int e = blk * 64 + mt * 16 + g + row * 8;
        if (e < p.n) {
            const int idx = p.ridx[e];
            ld2(p, e, idx, k0,     v[row][0], v[row][1]);
            ld2(p, e, idx, k0 + 8, v[row][2], v[row][3]);
        } else {
            v[row][0] = v[row][1] = v[row][2] = v[row][3] = 0.f;
        }
    }
    uint4 H;
    H.x = h2pack(v[0][0], v[0][1]);
    H.y = h2pack(v[1][0], v[1][1]);
    H.z = h2pack(v[0][2], v[0][3]);
    H.w = h2pack(v[1][2], v[1][3]);
    char* dst = (char*)g_a0 + (size_t)blk * 49152 + (size_t)fi * 16;
    *(uint4*)dst = H;
}

// ---------------- chunk MMA (A from smem plane, 2 m-tiles/warp) -------------
// A plane: per kt 2048B = [mt(4)][g(8)][t(4)] x 16B
template<int KT, int NT, bool DUAL>
__device__ __forceinline__ void mma_chunk_s(float accF[][4], float accR[][4],
                                            u32 abase, u32 wF, u32 wR,
                                            int N, int colOff, int mt0,
                                            int lane, int g, int t)
{
#pragma unroll
    for (int kt = 0; kt < KT; kt++) {
        const u32 aa = abase + kt * 2048 + (u32)(lane * 16) + (u32)(mt0 * 512);
        const uint4 ah0 = lds128(aa);
        const uint4 ah1 = lds128(aa + 512);
        const u32 aH0[4] = {ah0.x, ah0.y, ah0.z, ah0.w};
        const u32 aH1[4] = {ah1.x, ah1.y, ah1.z, ah1.w};
#pragma unroll
        for (int nt = 0; nt < NT; nt++) {
            const u32 off = (u32)(((kt * N + colOff + nt * 8 + g) * 4 + t) * 8);
            const uint2 wv = lds64(wF + off);
            mma_f16(accF[nt],      aH0, wv.x, wv.y);
            mma_f16(accF[NT + nt], aH1, wv.x, wv.y);
            if (DUAL) {
                const uint2 rv = lds64(wR + off);
                mma_f16(accR[nt],      aH0, rv.x, rv.y);
                mma_f16(accR[NT + nt], aH1, rv.x, rv.y);
            }
        }
    }
}

// ---------------- chunk MMA (A from gmem, layer 0, 2 m-tiles/warp) ----------
__device__ __forceinline__ void mma_chunk_r(float accF[][4], float accR[][4],
                                            const char* a0, int kc,
                                            u32 wF, u32 wR, int colOff, int mt0,
                                            int g, int t)
{
#pragma unroll
    for (int kt = 0; kt < 4; kt++) {
        const char* ap = a0 + (size_t)((((kc * 4 + kt) * 4 + mt0) * 8 + g) * 4 + t) * 16;
        const uint4 ah0 = *(const uint4*)ap;
        const uint4 ah1 = *(const uint4*)(ap + 512);
        const u32 aH0[4] = {ah0.x, ah0.y, ah0.z, ah0.w};
        const u32 aH1[4] = {ah1.x, ah1.y, ah1.z, ah1.w};
#pragma unroll
        for (int nt = 0; nt < 2; nt++) {
            const u32 off = (u32)(((kt * 64 + colOff + nt * 8 + g) * 4 + t) * 8);
            const uint2 wv = lds64(wF + off);
            mma_f16(accF[nt],     aH0, wv.x, wv.y);
            mma_f16(accF[2 + nt], aH1, wv.x, wv.y);
            const uint2 rv = lds64(wR + off);
            mma_f16(accR[nt],     aH0, rv.x, rv.y);
            mma_f16(accR[2 + nt], aH1, rv.x, rv.y);
        }
    }
}

// ---------------- epilogue: bias+relu+residual -> frag-packed A plane -------
template<int NT, bool DUAL>
__device__ __forceinline__ void epilogue(float accF[][4], float accR[][4],
                                         const float* bias, u32 sb, int colbase,
                                         int mt0, int g, int t)
{
#pragma unroll
    for (int mt = 0; mt < 2; mt++) {
#pragma unroll
        for (int nt = 0; nt < NT; nt++) {
            const int c0 = colbase + nt * 8 + t * 2;
            const float b0 = __ldg(bias + c0), b1 = __ldg(bias + c0 + 1);
            const int ai = mt * NT + nt;
            float v0 = fmaxf(accF[ai][0] + b0, 0.f);
            float v1 = fmaxf(accF[ai][1] + b1, 0.f);
            float v2 = fmaxf(accF[ai][2] + b0, 0.f);
            float v3 = fmaxf(accF[ai][3] + b1, 0.f);
            const u32 fb = sb + OFF_AH + (u32)((c0 >> 4) * 2048)
                         + (u32)(((mt0 + mt) * 32 + g * 4 + ((c0 & 7) >> 1)) * 16) + (u32)(c0 & 8);
            if (DUAL) {
                v0 += accR[ai][0]; v1 += accR[ai][1];
                v2 += accR[ai][2]; v3 += accR[ai][3];
            } else {
                const u32 ph0 = lds32(fb);
                const u32 ph1 = lds32(fb + 4);
                v0 += hflo(ph0); v1 += hfhi(ph0);
                v2 += hflo(ph1); v3 += hfhi(ph1);
            }
            sts32(fb,     h2pack(v0, v1));
            sts32(fb + 4, h2pack(v2, v3));
        }
    }
}

// ---------------- main fused MLP (M=64, 256 threads, 2 CTAs/SM) -------------
__global__ void __launch_bounds__(NTH, 2) mlp_tc(P p)
{
    extern __shared__ char sm[];
    const u32 sb  = smem_u32(sm);
    const int tid = threadIdx.x;
    const int lane = tid & 31, warp = tid >> 5;
    const int mt0 = (warp & 1) * 2;      // first 16-row m-tile of this warp
    const int cq  = warp >> 1;           // column quarter 0-3
    const int g = lane >> 2, t = lane & 3;
    const int h   = blockIdx.y;
    const int blk = blockIdx.x;
    const int n0  = blk * 64;

    int* idx_s = (int*)(sm + OFF_IDX);
    if (tid < 64) idx_s[tid] = (n0 + tid < p.n) ? p.ridx[n0 + tid] : 0;

    const char* gw = (const char*)g_w + (size_t)h * HB;
    const char* a0 = (const char*)g_a0 + (size_t)blk * 49152;

    int cc = 0;
#define WBUF(i)  (sb + OFF_W + (u32)(((i) & 1) * 16384))

    // prefetch L0 (q=0, kc=0): [fc][res]
    {
        u32 b = WBUF(0);
        stage(b,        gw + B0, 8192, tid);
        stage(b + 8192, gw + B1, 8192, tid);
        COMMIT();
    }

    // ===== layer 0: 384(pad) -> 256, fc + res, n-quarters, 24 phases =====
    for (int q = 0; q < 4; q++) {
        float accF[4][4], accR[4][4];
#pragma unroll
        for (int i = 0; i < 4; i++)
#pragma unroll
            for (int j = 0; j < 4; j++) { accF[i][j] = 0.f; accR[i][j] = 0.f; }
        for (int kc = 0; kc < 6; kc++) {
            WAITG0();
            __syncthreads();
            u32 nxt = WBUF(cc + 1);
            int nq = q, nkc = kc + 1;
            if (nkc == 6) { nq = q + 1; nkc = 0; }
            if (nq < 4) {
                stage(nxt,        gw + B0 + (nkc * 4 + nq) * 8192, 8192, tid);
                stage(nxt + 8192, gw + B1 + (nkc * 4 + nq) * 8192, 8192, tid);
            } else {
                stage(nxt, gw + B2, 16384, tid);
            }
            COMMIT();
            const u32 wB = WBUF(cc);
            mma_chunk_r(accF, accR, a0, kc, wB, wB + 8192, cq * 16, mt0, g, t);
            cc++;
        }
        __syncthreads();
        epilogue<2, true>(accF, accR, p.fcb0 + h * 256, sb, q * 64 + cq * 16, mt0, g, t);
        __syncthreads();
    }

    // ===== layers 1-3: 256 -> 256, identity residual, 8 phases each =====
    for (int l = 0; l < 3; l++) {
        const float* bias = (l == 0 ? p.fcb1 : l == 1 ? p.fcb2 : p.fcb3) + h * 256;
        const char* wl = gw + B2 + (size_t)l * 131072;
        float acc[16][4];
#pragma unroll
        for (int i = 0; i < 16; i++)
#pragma unroll
            for (int j = 0; j < 4; j++) acc[i][j] = 0.f;
        for (int c = 0; c < 8; c++) {
            WAITG0();
            __syncthreads();
            u32 nxt = WBUF(cc + 1);
            if (c < 7) {
                stage(nxt, wl + (c + 1) * 16384, 16384, tid);
            } else if (l < 2) {
                stage(nxt, wl + 131072, 16384, tid);
            } else {
                stage(nxt,        gw + B5, 8192, tid);
                stage(nxt + 8192, gw + B6, 8192, tid);
            }
            COMMIT();
            mma_chunk_s<2, 8, false>(acc, acc, sb + OFF_AH + c * 4096,
                                     WBUF(cc), 0, 256, cq * 64, mt0, lane, g, t);
            cc++;
        }
        __syncthreads();
        epilogue<8, false>(acc, acc, bias, sb, cq * 64, mt0, g, t);
        __syncthreads();
    }

    // ===== layer 4: 256 -> 128, fc + res, 8 phases =====
    {
        float accF[8][4], accR[8][4];
#pragma unroll
        for (int i = 0; i < 8; i++)
#pragma unroll
            for (int j = 0; j < 4; j++) { accF[i][j] = 0.f; accR[i][j] = 0.f; }
        for (int c = 0; c < 8; c++) {
            WAITG0();
            __syncthreads();
            u32 nxt = WBUF(cc + 1);
            if (c < 7) {
                stage(nxt,        gw + B5 + (c + 1) * 8192, 8192, tid);
                stage(nxt + 8192, gw + B6 + (c + 1) * 8192, 8192, tid);
            } else {
                stage(nxt, gw + B7, 16384, tid);
            }
            COMMIT();
            const u32 wB = WBUF(cc);
            mma_chunk_s<2, 4, true>(accF, accR, sb + OFF_AH + c * 4096,
                                    wB, wB + 8192, 128, cq * 32, mt0, lane, g, t);
            cc++;
        }
        __syncthreads();
        epilogue<4, true>(accF, accR, p.fcb4 + h * 128, sb, cq * 32, mt0, g, t);
        __syncthreads();
    }

    // ===== layer 5: 128 -> 128, identity, 2 phases =====
    {
        float acc[8][4];
#pragma unroll
        for (int i = 0; i < 8; i++)
#pragma unroll
            for (int j = 0; j < 4; j++) acc[i][j] = 0.f;
        for (int c = 0; c < 2; c++) {
            WAITG0();
            __syncthreads();
            u32 nxt = WBUF(cc + 1);
            if (c < 1) {
                stage(nxt, gw + B7 + 16384, 16384, tid);
            } else {
                stage(nxt,        gw + B8, 8192, tid);
                stage(nxt + 8192, gw + B9, 8192, tid);
            }
            COMMIT();
            mma_chunk_s<4, 4, false>(acc, acc, sb + OFF_AH + c * 8192,
                                     WBUF(cc), 0, 128, cq * 32, mt0, lane, g, t);
            cc++;
        }
        __syncthreads();
        epilogue<4, false>(acc, acc, p.fcb5 + h * 128, sb, cq * 32, mt0, g, t);
        __syncthreads();
    }

    // ===== layer 6: 128 -> 64, fc + res, 2 phases =====
    {
        float accF[4][4], accR[4][4];
#pragma unroll
        for (int i = 0; i < 4; i++)
#pragma unroll
            for (int j = 0; j < 4; j++) { accF[i][j] = 0.f; accR[i][j] = 0.f; }
        for (int c = 0; c < 2; c++) {
            WAITG0();
            __syncthreads();
            if (c < 1) {
                u32 nxt = WBUF(cc + 1);
                stage(nxt,        gw + B8 + 8192, 8192, tid);
                stage(nxt + 8192, gw + B9 + 8192, 8192, tid);
                COMMIT();
            }
            const u32 wB = WBUF(cc);
            mma_chunk_s<4, 2, true>(accF, accR, sb + OFF_AH + c * 8192,
                                    wB, wB + 8192, 64, cq * 16, mt0, lane, g, t);
            cc++;
        }
        __syncthreads();
        epilogue<2, true>(accF, accR, p.fcb6 + h * 64, sb, cq * 16, mt0, g, t);
        __syncthreads();
    }

    // ===== output head: gate = h . outW + outb =====
    if (tid < 64) {
        const int r = tid, e = n0 + r;
        if (e < p.n) {
            const int mt = r >> 4, g2 = r & 7, rh = (r & 15) >> 3;
            float acc = 0.f;
#pragma unroll
            for (int c = 0; c < 64; c += 2) {
                const u32 fb = sb + OFF_AH + (u32)((c >> 4) * 2048)
                             + (u32)((mt * 32 + g2 * 4 + ((c & 7) >> 1)) * 16)
                             + (u32)((c & 8) + rh * 4);
                const u32 ph = lds32(fb);
                acc = fmaf(hflo(ph), __ldg(p.outW + h * 64 + c), acc);
                acc = fmaf(hfhi(ph), __ldg(p.outW + h * 64 + c + 1), acc);
            }
            const float gate = acc + __ldg(p.outb + h);
            g_gate[h * p.n + e] = gate;
            atomicMax(&g_segmax[h * p.c + idx_s[r]], fkey(gate));
        }
    }
}

// ---------------- segment softmax epilogue ---------------------------------
__global__ void init_seg(int total)
{
    const int i = blockIdx.x * blockDim.x + threadIdx.x;
    if (i < total) { g_segmax[i] = 0u; g_segsum[i] = 0.f; }
}

__global__ void exp_kernel(const int* __restrict__ ridx, int n, int c)
{
    const int i = blockIdx.x * blockDim.x + threadIdx.x;
    if (i >= NH * n) return;
    const int hh = i / n;
    const int nn = i - hh * n;
    const int r  = ridx[nn];
    const float m = funkey(g_segmax[hh * c + r]);
    const float e = expf(g_gate[i] - m);
    g_gate[i] = e;
    atomicAdd(&g_segsum[hh * c + r], e);
}

__global__ void out_kernel(const int* __restrict__ ridx,
                           float* __restrict__ out, int n, int c)
{
    const int nn = blockIdx.x * blockDim.x + threadIdx.x;
    if (nn >= n) return;
    const int r = ridx[nn];
    float s = 0.f;
#pragma unroll
    for (int hh = 0; hh < NH; ++hh)
        s += g_gate[hh * n + nn] / (g_segsum[hh * c + r] + 1e-13f);
    out[nn] = s * (1.0f / 3.0f);
}

extern "C" void kernel_launch(void* const* d_in, const int* in_sizes, int n_in,
                              void* d_out, int out_size)
{
    P p;
    p.elem  = (const float*)d_in[0];
    p.ridx  = (const int*)  d_in[1];
    p.remb  = (const float*)d_in[2];
    p.fcW0  = (const float*)d_in[3];  p.fcb0 = (const float*)d_in[4];
    p.fcW1  = (const float*)d_in[5];  p.fcb1 = (const float*)d_in[6];
    p.fcW2  = (const float*)d_in[7];  p.fcb2 = (const float*)d_in[8];
    p.fcW3  = (const float*)d_in[9];  p.fcb3 = (const float*)d_in[10];
    p.fcW4  = (const float*)d_in[11]; p.fcb4 = (const float*)d_in[12];
    p.fcW5  = (const float*)d_in[13]; p.fcb5 = (const float*)d_in[14];
    p.fcW6  = (const float*)d_in[15]; p.fcb6 = (const float*)d_in[16];
    p.resW0 = (const float*)d_in[17];
    p.resW4 = (const float*)d_in[18];
    p.resW6 = (const float*)d_in[19];
    p.outW  = (const float*)d_in[20];
    p.outb  = (const float*)d_in[21];
    p.n = in_sizes[1];
    p.c = in_sizes[2] / 128;

    static bool init_done = false;
    if (!init_done) {
        cudaFuncSetAttribute(mlp_tc, cudaFuncAttributeMaxDynamicSharedMemorySize, SMEMSZ);
        init_done = true;
    }

    const int nblk = (p.n + 63) / 64;

    prep_w<<<dim3(480, NH), 256>>>(p);
    prep_a0<<<dim3(12, nblk), 256>>>(p);

    const int segs = NH * p.c;
    init_seg<<<(segs + 255) / 256, 256>>>(segs);

    mlp_tc<<<dim3(nblk, NH), NTH, SMEMSZ>>>(p);

    const int tot = NH * p.n;
    exp_kernel<<<(tot + 255) / 256, 256>>>(p.ridx, p.n, p.c);
    out_kernel<<<(p.n + 255) / 256, 256>>>(p.ridx, (float*)d_out, p.n, p.c);
}